// round 4
// baseline (speedup 1.0000x reference)
#include <cuda_runtime.h>
#include <math.h>

#define Bb 16
#define II 512
#define HH 1024
#define BH (Bb*HH)            // 16384

#define NPROD 112
#define NCONS 184
#define NBLK  (NPROD + NCONS) // 296 = 2 blocks/SM on 148 SMs
#define NJT   64              // j-tiles of 16 rows
#define GITEMS (NJT * 12)     // 768 gate items: (jt, kc, g)
#define TITEMS 2048           // trace items: (j8, b)
#define TCONS  1472           // first 1472 -> consumers (8 each), rest -> producers

// Output offsets (floats): h, c, e_w_ix, e_w_ih, e_b_i, e_w_fx, e_w_fh, e_b_f, e_w_cx, e_w_ch, e_b_c
#define OFF_H     0
#define OFF_C     16384
#define OFF_EWIX  32768
#define OFF_EWIH  8421376
#define OFF_EBI   25198592
#define OFF_EWFX  25214976
#define OFF_EWFH  33603584
#define OFF_EBF   50380800
#define OFF_EWCX  50397184
#define OFF_EWCH  58785792
#define OFF_EBC   75563008

// Scratch (no allocation allowed)
__device__ float g_part[3][4 * BH];   // partial pre-activations per K-chunk
__device__ int   g_cnt[NJT];          // arrivals per j-tile (12 = ready)

#define FMA4(A, Z, ACC)                         \
    ACC = fmaf((A).x, (Z).x, ACC);              \
    ACC = fmaf((A).y, (Z).y, ACC);              \
    ACC = fmaf((A).z, (Z).z, ACC);              \
    ACC = fmaf((A).w, (Z).w, ACC);

__global__ void reset_kernel() {
    if (threadIdx.x < NJT) g_cnt[threadIdx.x] = 0;
}

// ---------------------------------------------------------------------------
// Producer: one gate item = (jt: 16 j-rows, g: gate, kc: K-chunk of 512).
// 8 warps x 2 j-rows x 16 batches. Operand chunk staged in 32KB SMEM.
// ---------------------------------------------------------------------------
__device__ __forceinline__ void gates_item(
    int id, float4* sz, int tid,
    const float* __restrict__ x, const float* __restrict__ h_last,
    const float* w_ix, const float* w_fx, const float* w_ox, const float* w_cx,
    const float* w_ih, const float* w_fh, const float* w_oh, const float* w_ch)
{
    const int jt = id / 12;
    const int r  = id % 12;
    const int kc = r >> 2;
    const int g  = r & 3;

    // stage operand chunk (16 b x 128 float4)
    if (kc == 0) {
        const float4* src = (const float4*)x;
#pragma unroll
        for (int t = tid; t < 2048; t += 256) sz[t] = src[t];
    } else {
        const float4* src = (const float4*)h_last;
        const int off = (kc - 1) * 128;
#pragma unroll
        for (int t = tid; t < 2048; t += 256) {
            int b = t >> 7, kq = t & 127;
            sz[t] = src[b * 256 + off + kq];
        }
    }
    __syncthreads();

    const float* wbase;
    if (kc == 0) wbase = (g == 0) ? w_ix : (g == 1) ? w_fx : (g == 2) ? w_ox : w_cx;
    else         wbase = (g == 0) ? w_ih : (g == 1) ? w_fh : (g == 2) ? w_oh : w_ch;
    const int rowlen = (kc == 0) ? II : HH;
    const int koff   = (kc == 0) ? 0 : (kc - 1) * 512;

    const int warp = tid >> 5;
    const int lane = tid & 31;
    const int j0   = jt * 16 + warp * 2;

    const float4* w0 = (const float4*)(wbase + (size_t)j0 * rowlen + koff);
    const float4* w1 = (const float4*)(wbase + (size_t)(j0 + 1) * rowlen + koff);

    float acc0[Bb], acc1[Bb];
#pragma unroll
    for (int b = 0; b < Bb; b++) { acc0[b] = 0.f; acc1[b] = 0.f; }

#pragma unroll
    for (int it = 0; it < 4; it++) {
        const int k4 = it * 32 + lane;
        float4 a0 = w0[k4];
        float4 a1 = w1[k4];
#pragma unroll
        for (int b = 0; b < Bb; b++) {
            float4 z = sz[b * 128 + k4];
            FMA4(a0, z, acc0[b]);
            FMA4(a1, z, acc1[b]);
        }
    }

#pragma unroll
    for (int off = 16; off; off >>= 1)
#pragma unroll
        for (int b = 0; b < Bb; b++) {
            acc0[b] += __shfl_xor_sync(0xffffffffu, acc0[b], off);
            acc1[b] += __shfl_xor_sync(0xffffffffu, acc1[b], off);
        }

    if (lane == 0) {
        float* dst = g_part[kc] + g * BH;
#pragma unroll
        for (int b = 0; b < Bb; b++) {
            dst[b * HH + j0]     = acc0[b];
            dst[b * HH + j0 + 1] = acc1[b];
        }
        __threadfence();
    }
    __syncthreads();
    if (tid == 0) atomicAdd(&g_cnt[jt], 1);
    __syncthreads();
}

// ---------------------------------------------------------------------------
// Consumer: one trace item = (b, 8 j-rows). Waits for the owning j-tile's
// 12 gate arrivals, computes activations/coefs + h/c/e_b, streams 6 traces.
// ---------------------------------------------------------------------------
__device__ __forceinline__ void trace_item(
    int id, float4* sz, float4* scf, int tid,
    const float* __restrict__ x, const float* __restrict__ h_last,
    const float* __restrict__ c_last,
    const float* __restrict__ b_i, const float* __restrict__ b_f,
    const float* __restrict__ b_o, const float* __restrict__ b_c,
    const float* __restrict__ eb_i, const float* __restrict__ eb_f,
    const float* __restrict__ eb_c,
    const float* __restrict__ e_ix, const float* __restrict__ e_ih,
    const float* __restrict__ e_fx, const float* __restrict__ e_fh,
    const float* __restrict__ e_cx, const float* __restrict__ e_ch,
    float* __restrict__ out)
{
    const int j8 = id >> 4;       // 0..127
    const int b  = id & 15;
    const int j0 = j8 * 8;

    float4* sx = sz;              // 128 float4
    float4* sh = sz + 128;        // 256 float4

    if (tid < 128) sx[tid] = ((const float4*)(x + b * II))[tid];
    sh[tid] = ((const float4*)(h_last + b * HH))[tid];

    if (tid == 0) {
        while (atomicAdd(&g_cnt[j8 >> 1], 0) < 12) __nanosleep(64);
        __threadfence();
    }
    __syncthreads();

    if (tid < 8) {
        const int j   = j0 + tid;
        const int idx = b * HH + j;

        float pi = g_part[0][0 * BH + idx] + g_part[1][0 * BH + idx] + g_part[2][0 * BH + idx] + b_i[j];
        float pf = g_part[0][1 * BH + idx] + g_part[1][1 * BH + idx] + g_part[2][1 * BH + idx] + b_f[j];
        float po = g_part[0][2 * BH + idx] + g_part[1][2 * BH + idx] + g_part[2][2 * BH + idx] + b_o[j];
        float pc = g_part[0][3 * BH + idx] + g_part[1][3 * BH + idx] + g_part[2][3 * BH + idx] + b_c[j];

        float i  = 1.f / (1.f + expf(-pi));
        float f  = 1.f / (1.f + expf(-pf));
        float o  = 1.f / (1.f + expf(-po));
        float ch = tanhf(pc);
        float cl = c_last[idx];

        float c = fmaf(f, cl, i * ch);
        float h = o * c;
        float di  = i * (1.f - i);
        float df  = f * (1.f - f);
        float dch = 1.f - ch * ch;
        float ai = di * ch;
        float af = df * cl;
        float ac = dch * i;

        out[OFF_H + idx]   = h;
        out[OFF_C + idx]   = c;
        out[OFF_EBI + idx] = fmaf(eb_i[idx], f, ai);
        out[OFF_EBF + idx] = fmaf(eb_f[idx], f, af);
        out[OFF_EBC + idx] = fmaf(eb_c[idx], f, ac);
        scf[tid] = make_float4(f, ai, af, ac);
    }
    __syncthreads();

    const size_t baseH = (size_t)(b * HH + j0) * (HH / 4);
    const size_t baseI = (size_t)(b * HH + j0) * (II / 4);

#define TRACE_H(SRC, OFF, SEL)                                              \
    {                                                                       \
        const float4* ein = (const float4*)(SRC) + baseH;                   \
        float4* eo = (float4*)(out + (OFF)) + baseH;                        \
        _Pragma("unroll 8")                                                 \
        for (int t = tid; t < 8 * (HH / 4); t += 256) {                     \
            float4 cf = scf[t >> 8];                                        \
            float fv = cf.x, a = cf.SEL;                                    \
            float4 e  = __ldcs(ein + t);                                    \
            float4 hv = sh[t & 255];                                        \
            float4 rr;                                                      \
            rr.x = fmaf(e.x, fv, a * hv.x);                                 \
            rr.y = fmaf(e.y, fv, a * hv.y);                                 \
            rr.z = fmaf(e.z, fv, a * hv.z);                                 \
            rr.w = fmaf(e.w, fv, a * hv.w);                                 \
            __stcs(eo + t, rr);                                             \
        }                                                                   \
    }

#define TRACE_X(SRC, OFF, SEL)                                              \
    {                                                                       \
        const float4* ein = (const float4*)(SRC) + baseI;                   \
        float4* eo = (float4*)(out + (OFF)) + baseI;                        \
        _Pragma("unroll 4")                                                 \
        for (int t = tid; t < 8 * (II / 4); t += 256) {                     \
            float4 cf = scf[t >> 7];                                        \
            float fv = cf.x, a = cf.SEL;                                    \
            float4 e  = __ldcs(ein + t);                                    \
            float4 xv = sx[t & 127];                                        \
            float4 rr;                                                      \
            rr.x = fmaf(e.x, fv, a * xv.x);                                 \
            rr.y = fmaf(e.y, fv, a * xv.y);                                 \
            rr.z = fmaf(e.z, fv, a * xv.z);                                 \
            rr.w = fmaf(e.w, fv, a * xv.w);                                 \
            __stcs(eo + t, rr);                                             \
        }                                                                   \
    }

    TRACE_H(e_ih, OFF_EWIH, y)
    TRACE_H(e_fh, OFF_EWFH, z)
    TRACE_H(e_ch, OFF_EWCH, w)
    TRACE_X(e_ix, OFF_EWIX, y)
    TRACE_X(e_fx, OFF_EWFX, z)
    TRACE_X(e_cx, OFF_EWCX, w)
    __syncthreads();
}

// ---------------------------------------------------------------------------
__global__ __launch_bounds__(256, 2) void fused_kernel(
    const float* __restrict__ x, const float* __restrict__ h_last,
    const float* __restrict__ c_last,
    const float* w_ix, const float* w_fx, const float* w_ox, const float* w_cx,
    const float* w_ih, const float* w_fh, const float* w_oh, const float* w_ch,
    const float* __restrict__ b_i, const float* __restrict__ b_f,
    const float* __restrict__ b_o, const float* __restrict__ b_c,
    const float* __restrict__ eb_i, const float* __restrict__ eb_f,
    const float* __restrict__ eb_c,
    const float* __restrict__ e_ix, const float* __restrict__ e_ih,
    const float* __restrict__ e_fx, const float* __restrict__ e_fh,
    const float* __restrict__ e_cx, const float* __restrict__ e_ch,
    float* __restrict__ out)
{
    __shared__ float4 sz[2048];   // 32KB: producer staging / consumer sx+sh
    __shared__ float4 scf[8];

    const int blk = blockIdx.x;
    const int tid = threadIdx.x;

    if (blk < NPROD) {
        // produce all gate items (j-major order -> low j ready first)
        for (int id = blk; id < GITEMS; id += NPROD)
            gates_item(id, sz, tid, x, h_last,
                       w_ix, w_fx, w_ox, w_cx, w_ih, w_fh, w_oh, w_ch);
        // then take the tail trace items (high j; ready by now)
        for (int id = TCONS + blk; id < TITEMS; id += NPROD)
            trace_item(id, sz, scf, tid, x, h_last, c_last,
                       b_i, b_f, b_o, b_c, eb_i, eb_f, eb_c,
                       e_ix, e_ih, e_fx, e_fh, e_cx, e_ch, out);
    } else {
        const int c = blk - NPROD;
        for (int id = c; id < TCONS; id += NCONS)
            trace_item(id, sz, scf, tid, x, h_last, c_last,
                       b_i, b_f, b_o, b_c, eb_i, eb_f, eb_c,
                       e_ix, e_ih, e_fx, e_fh, e_cx, e_ch, out);
    }
}

// ---------------------------------------------------------------------------
extern "C" void kernel_launch(void* const* d_in, const int* in_sizes, int n_in,
                              void* d_out, int out_size)
{
    const float* x      = (const float*)d_in[0];
    const float* w_ix   = (const float*)d_in[1];
    const float* w_ih   = (const float*)d_in[2];
    const float* b_i    = (const float*)d_in[3];
    const float* w_fx   = (const float*)d_in[4];
    const float* w_fh   = (const float*)d_in[5];
    const float* b_f    = (const float*)d_in[6];
    const float* w_ox   = (const float*)d_in[7];
    const float* w_oh   = (const float*)d_in[8];
    const float* b_o    = (const float*)d_in[9];
    const float* w_cx   = (const float*)d_in[10];
    const float* w_ch   = (const float*)d_in[11];
    const float* b_c    = (const float*)d_in[12];
    const float* h_last = (const float*)d_in[13];
    const float* c_last = (const float*)d_in[14];
    const float* e_w_ix = (const float*)d_in[15];
    const float* e_w_ih = (const float*)d_in[16];
    const float* e_b_i  = (const float*)d_in[17];
    const float* e_w_fx = (const float*)d_in[18];
    const float* e_w_fh = (const float*)d_in[19];
    const float* e_b_f  = (const float*)d_in[20];
    const float* e_w_cx = (const float*)d_in[21];
    const float* e_w_ch = (const float*)d_in[22];
    const float* e_b_c  = (const float*)d_in[23];
    float* out = (float*)d_out;

    reset_kernel<<<1, 64>>>();
    fused_kernel<<<NBLK, 256>>>(x, h_last, c_last,
                                w_ix, w_fx, w_ox, w_cx,
                                w_ih, w_fh, w_oh, w_ch,
                                b_i, b_f, b_o, b_c,
                                e_b_i, e_b_f, e_b_c,
                                e_w_ix, e_w_ih, e_w_fx, e_w_fh,
                                e_w_cx, e_w_ch, out);
}

// round 5
// speedup vs baseline: 1.8152x; 1.8152x over previous
#include <cuda_runtime.h>
#include <math.h>

#define Bb 16
#define II 512
#define HH 1024
#define BH (Bb*HH)            // 16384

// Output offsets (floats): h, c, e_w_ix, e_w_ih, e_b_i, e_w_fx, e_w_fh, e_b_f, e_w_cx, e_w_ch, e_b_c
#define OFF_H     0
#define OFF_C     16384
#define OFF_EWIX  32768
#define OFF_EWIH  8421376
#define OFF_EBI   25198592
#define OFF_EWFX  25214976
#define OFF_EWFH  33603584
#define OFF_EBF   50380800
#define OFF_EWCX  50397184
#define OFF_EWCH  58785792
#define OFF_EBC   75563008

// Scratch (no allocation allowed)
__device__ float g_part[3][4 * BH];   // partial pre-activations per K-chunk

struct GatePtrs {
    const float* wx[4];
    const float* wh[4];
};

#define FMA4(A, Z, ACC)                         \
    ACC = fmaf((A).x, (Z).x, ACC);              \
    ACC = fmaf((A).y, (Z).y, ACC);              \
    ACC = fmaf((A).z, (Z).z, ACC);              \
    ACC = fmaf((A).w, (Z).w, ACC);

// ---------------------------------------------------------------------------
// Kernel 1: gate pre-activation partials.
// grid = (HH/16, 4 gates, 3 K-chunks), block = 256 (8 warps).
// Each warp: 2 consecutive j-rows x 16 batches (32 accumulators).
// Weight loads (8x LDG.128) are front-batched into registers before FMA.
// Cross-lane reduction: multi-value butterfly (31 SHFL total, value count
// halves per stage; lane L ends holding value bitrev5(L)).
// ---------------------------------------------------------------------------
__global__ __launch_bounds__(256, 2) void gates_kernel(
    const float* __restrict__ x, const float* __restrict__ h_last, GatePtrs p)
{
    __shared__ float4 sz[2048];    // 16 b * 128 float4 = 32KB

    const int tid   = threadIdx.x;
    const int chunk = blockIdx.z;
    const int g     = blockIdx.y;

    // Stage this chunk's operand: sz[b*128 + kq] = z[b][chunk_cols + kq*4..]
    if (chunk == 0) {
        const float4* src = (const float4*)x;
#pragma unroll
        for (int t = tid; t < 2048; t += 256) sz[t] = src[t];
    } else {
        const float4* src = (const float4*)h_last;
        const int off = (chunk - 1) * 128;
#pragma unroll
        for (int t = tid; t < 2048; t += 256) {
            int b = t >> 7, kq = t & 127;
            sz[t] = src[b * 256 + off + kq];
        }
    }
    __syncthreads();

    const int warp = tid >> 5;
    const int lane = tid & 31;
    const int j0   = blockIdx.x * 16 + warp * 2;

    const float* wbase;
    int rowlen, koff;
    if (chunk == 0) { wbase = p.wx[g]; rowlen = II; koff = 0; }
    else            { wbase = p.wh[g]; rowlen = HH; koff = (chunk - 1) * 512; }

    const float4* w0 = (const float4*)(wbase + (size_t)j0 * rowlen + koff);
    const float4* w1 = (const float4*)(wbase + (size_t)(j0 + 1) * rowlen + koff);

    // Front-batch all weight loads (8 independent LDG.128 in flight)
    float4 wr0[4], wr1[4];
#pragma unroll
    for (int it = 0; it < 4; it++) {
        wr0[it] = w0[it * 32 + lane];
        wr1[it] = w1[it * 32 + lane];
    }

    // a[m]: m = jj*16 + b  (jj in {0,1})
    float a[32];
#pragma unroll
    for (int m = 0; m < 32; m++) a[m] = 0.f;

#pragma unroll
    for (int it = 0; it < 4; it++) {
        const int k4 = it * 32 + lane;
#pragma unroll
        for (int b = 0; b < Bb; b++) {
            float4 z = sz[b * 128 + k4];
            FMA4(wr0[it], z, a[b]);
            FMA4(wr1[it], z, a[16 + b]);
        }
    }

    // Multi-value butterfly reduction: 5 stages, value count halves each.
#pragma unroll
    for (int k = 0; k < 5; k++) {
        const int d = 1 << k;
        const int n = 32 >> k;
        const bool hi = (lane >> k) & 1;
#pragma unroll
        for (int m = 0; m < 16; m++) {         // only m < n/2 active
            if (m < n / 2) {
                float mine = hi ? a[m] : a[m + n / 2];
                float got  = __shfl_xor_sync(0xffffffffu, mine, d);
                a[m] = (hi ? a[m + n / 2] : a[m]) + got;
            }
        }
    }

    // lane holds value index bitrev5(lane)
    const unsigned rev = __brev((unsigned)lane) >> 27;
    const int jj = rev >> 4;
    const int b  = rev & 15;
    g_part[chunk][g * BH + b * HH + j0 + jj] = a[0];
}

// ---------------------------------------------------------------------------
// Kernel 2: fused pointwise + HBM-bound trace update.
// grid = (HH/JT, Bb), block = 256. First JT threads reduce the partials,
// apply activations, write h/c/e_b outputs, stash coefficients in SMEM.
// Then all threads stream the 6 trace matrices at HBM roofline.
// ---------------------------------------------------------------------------
#define JT 8

__global__ __launch_bounds__(256) void trace_kernel(
    const float* __restrict__ x, const float* __restrict__ h_last,
    const float* __restrict__ c_last,
    const float* __restrict__ b_i, const float* __restrict__ b_f,
    const float* __restrict__ b_o, const float* __restrict__ b_c,
    const float* __restrict__ eb_i, const float* __restrict__ eb_f,
    const float* __restrict__ eb_c,
    const float* __restrict__ e_ix, const float* __restrict__ e_ih,
    const float* __restrict__ e_fx, const float* __restrict__ e_fh,
    const float* __restrict__ e_cx, const float* __restrict__ e_ch,
    float* __restrict__ out)
{
    __shared__ float4 sx[II / 4];   // 2KB
    __shared__ float4 sh[HH / 4];   // 4KB
    __shared__ float4 scf[JT];

    const int tid = threadIdx.x;
    const int b   = blockIdx.y;
    const int j0  = blockIdx.x * JT;

    for (int t = tid; t < II / 4; t += 256) sx[t] = ((const float4*)(x + b * II))[t];
    for (int t = tid; t < HH / 4; t += 256) sh[t] = ((const float4*)(h_last + b * HH))[t];

    if (tid < JT) {
        const int j   = j0 + tid;
        const int idx = b * HH + j;

        float pi = g_part[0][0 * BH + idx] + g_part[1][0 * BH + idx] + g_part[2][0 * BH + idx] + b_i[j];
        float pf = g_part[0][1 * BH + idx] + g_part[1][1 * BH + idx] + g_part[2][1 * BH + idx] + b_f[j];
        float po = g_part[0][2 * BH + idx] + g_part[1][2 * BH + idx] + g_part[2][2 * BH + idx] + b_o[j];
        float pc = g_part[0][3 * BH + idx] + g_part[1][3 * BH + idx] + g_part[2][3 * BH + idx] + b_c[j];

        float i  = 1.f / (1.f + expf(-pi));
        float f  = 1.f / (1.f + expf(-pf));
        float o  = 1.f / (1.f + expf(-po));
        float ch = tanhf(pc);
        float cl = c_last[idx];

        float c = fmaf(f, cl, i * ch);
        float h = o * c;
        float di  = i * (1.f - i);
        float df  = f * (1.f - f);
        float dch = 1.f - ch * ch;
        float ai = di * ch;
        float af = df * cl;
        float ac = dch * i;

        out[OFF_H + idx]   = h;
        out[OFF_C + idx]   = c;
        out[OFF_EBI + idx] = fmaf(eb_i[idx], f, ai);
        out[OFF_EBF + idx] = fmaf(eb_f[idx], f, af);
        out[OFF_EBC + idx] = fmaf(eb_c[idx], f, ac);
        scf[tid] = make_float4(f, ai, af, ac);
    }
    __syncthreads();

    const size_t baseH = (size_t)(b * HH + j0) * (HH / 4);
    const size_t baseI = (size_t)(b * HH + j0) * (II / 4);

#define TRACE_H(SRC, OFF, SEL)                                              \
    {                                                                       \
        const float4* ein = (const float4*)(SRC) + baseH;                   \
        float4* eo = (float4*)(out + (OFF)) + baseH;                        \
        _Pragma("unroll 8")                                                 \
        for (int t = tid; t < JT * (HH / 4); t += 256) {                    \
            float4 cf = scf[t >> 8];                                        \
            float fv = cf.x, aa = cf.SEL;                                   \
            float4 e  = __ldcs(ein + t);                                    \
            float4 hv = sh[t & 255];                                        \
            float4 rr;                                                      \
            rr.x = fmaf(e.x, fv, aa * hv.x);                                \
            rr.y = fmaf(e.y, fv, aa * hv.y);                                \
            rr.z = fmaf(e.z, fv, aa * hv.z);                                \
            rr.w = fmaf(e.w, fv, aa * hv.w);                                \
            __stcs(eo + t, rr);                                             \
        }                                                                   \
    }

#define TRACE_X(SRC, OFF, SEL)                                              \
    {                                                                       \
        const float4* ein = (const float4*)(SRC) + baseI;                   \
        float4* eo = (float4*)(out + (OFF)) + baseI;                        \
        _Pragma("unroll 4")                                                 \
        for (int t = tid; t < JT * (II / 4); t += 256) {                    \
            float4 cf = scf[t >> 7];                                        \
            float fv = cf.x, aa = cf.SEL;                                   \
            float4 e  = __ldcs(ein + t);                                    \
            float4 xv = sx[t & 127];                                        \
            float4 rr;                                                      \
            rr.x = fmaf(e.x, fv, aa * xv.x);                                \
            rr.y = fmaf(e.y, fv, aa * xv.y);                                \
            rr.z = fmaf(e.z, fv, aa * xv.z);                                \
            rr.w = fmaf(e.w, fv, aa * xv.w);                                \
            __stcs(eo + t, rr);                                             \
        }                                                                   \
    }

    TRACE_H(e_ih, OFF_EWIH, y)
    TRACE_H(e_fh, OFF_EWFH, z)
    TRACE_H(e_ch, OFF_EWCH, w)
    TRACE_X(e_ix, OFF_EWIX, y)
    TRACE_X(e_fx, OFF_EWFX, z)
    TRACE_X(e_cx, OFF_EWCX, w)
}

// ---------------------------------------------------------------------------
extern "C" void kernel_launch(void* const* d_in, const int* in_sizes, int n_in,
                              void* d_out, int out_size)
{
    const float* x      = (const float*)d_in[0];
    const float* w_ix   = (const float*)d_in[1];
    const float* w_ih   = (const float*)d_in[2];
    const float* b_i    = (const float*)d_in[3];
    const float* w_fx   = (const float*)d_in[4];
    const float* w_fh   = (const float*)d_in[5];
    const float* b_f    = (const float*)d_in[6];
    const float* w_ox   = (const float*)d_in[7];
    const float* w_oh   = (const float*)d_in[8];
    const float* b_o    = (const float*)d_in[9];
    const float* w_cx   = (const float*)d_in[10];
    const float* w_ch   = (const float*)d_in[11];
    const float* b_c    = (const float*)d_in[12];
    const float* h_last = (const float*)d_in[13];
    const float* c_last = (const float*)d_in[14];
    const float* e_w_ix = (const float*)d_in[15];
    const float* e_w_ih = (const float*)d_in[16];
    const float* e_b_i  = (const float*)d_in[17];
    const float* e_w_fx = (const float*)d_in[18];
    const float* e_w_fh = (const float*)d_in[19];
    const float* e_b_f  = (const float*)d_in[20];
    const float* e_w_cx = (const float*)d_in[21];
    const float* e_w_ch = (const float*)d_in[22];
    const float* e_b_c  = (const float*)d_in[23];
    float* out = (float*)d_out;

    GatePtrs p;
    p.wx[0] = w_ix; p.wx[1] = w_fx; p.wx[2] = w_ox; p.wx[3] = w_cx;
    p.wh[0] = w_ih; p.wh[1] = w_fh; p.wh[2] = w_oh; p.wh[3] = w_ch;

    dim3 g1(HH / 16, 4, 3);
    gates_kernel<<<g1, 256>>>(x, h_last, p);

    dim3 g3(HH / JT, Bb);
    trace_kernel<<<g3, 256>>>(x, h_last, c_last, b_i, b_f, b_o, b_c,
                              e_b_i, e_b_f, e_b_c,
                              e_w_ix, e_w_ih, e_w_fx, e_w_fh,
                              e_w_cx, e_w_ch, out);
}